// round 1
// baseline (speedup 1.0000x reference)
#include <cuda_runtime.h>

#define BATCH 2048
#define NE    2048
#define NDIMS 128
#define SPEC_C 6.5f

#define TILE   128
#define DCHUNK 32
#define SROW   132   // padded smem row stride (floats), multiple of 4 for LDS.128

// Scratch (device globals: allocation-free rule)
__device__ float g_xs[BATCH * NDIMS];   // attn-scaled inputs
__device__ float g_es[NE * NDIMS];      // attn-scaled exemplars
__device__ float g_sumx[BATCH];         // row sums of g_xs
__device__ float g_sume[NE];            // row sums of g_es

// ---------------------------------------------------------------------------
// Pre-scale: Xs = attn*X, Es = attn*E, plus per-row sums. One warp per row.
// ---------------------------------------------------------------------------
__global__ void prep_kernel(const float* __restrict__ X,
                            const float* __restrict__ E,
                            const float* __restrict__ attn) {
    const int warp = threadIdx.x >> 5;
    const int lane = threadIdx.x & 31;
    const int row  = blockIdx.x * 8 + warp;

    const float* src  = blockIdx.y ? E : X;
    float*       dst  = blockIdx.y ? g_es : g_xs;
    float*       dsum = blockIdx.y ? g_sume : g_sumx;

    float4 x = reinterpret_cast<const float4*>(src + (size_t)row * NDIMS)[lane];
    float4 a = reinterpret_cast<const float4*>(attn)[lane];
    float4 s = make_float4(x.x * a.x, x.y * a.y, x.z * a.z, x.w * a.w);
    reinterpret_cast<float4*>(dst + (size_t)row * NDIMS)[lane] = s;

    float t = (s.x + s.y) + (s.z + s.w);
    #pragma unroll
    for (int off = 16; off > 0; off >>= 1)
        t += __shfl_xor_sync(0xffffffffu, t, off);
    if (lane == 0) dsum[row] = t;
}

// ---------------------------------------------------------------------------
// Main: out[b,e] = exp(-C * (SumX[b] + SumE[e] - 2*sum_d min(Xs[b,d],Es[e,d])))
// 128x128 tile / block, 256 threads, 8x8 micro-tile per thread.
// Thread (ty,tx) in 16x16 grid. Rows: b0 + ty*4 + {0..3} and b0+64+ty*4+{0..3}
// (two contiguous float4 groups -> conflict-free LDS.128, coalesced STG.128).
// ---------------------------------------------------------------------------
__global__ __launch_bounds__(256, 2)
void alcove_kernel(float* __restrict__ out) {
    __shared__ float sx[DCHUNK * SROW];
    __shared__ float se[DCHUNK * SROW];

    const int tid = threadIdx.x;
    const int tx  = tid & 15;
    const int ty  = tid >> 4;
    const int b0  = blockIdx.y * TILE;
    const int e0  = blockIdx.x * TILE;

    float acc[8][8];
    #pragma unroll
    for (int i = 0; i < 8; ++i)
        #pragma unroll
        for (int j = 0; j < 8; ++j) acc[i][j] = 0.f;

    // staging decomposition: 256 threads cover 32 rows x 8 d-quads per pass
    const int q = tid & 7;   // d-quad within chunk (8 quads * 4 = 32 dims)
    const int r = tid >> 3;  // row within 32-row pass

    for (int dc = 0; dc < NDIMS; dc += DCHUNK) {
        __syncthreads();
        // Stage [row][d] -> smem [d][row] (transpose) for x and e tiles
        #pragma unroll
        for (int p = 0; p < 4; ++p) {
            const int row = r + p * 32;
            const float4 vx = *reinterpret_cast<const float4*>(
                &g_xs[(size_t)(b0 + row) * NDIMS + dc + q * 4]);
            const float4 ve = *reinterpret_cast<const float4*>(
                &g_es[(size_t)(e0 + row) * NDIMS + dc + q * 4]);
            sx[(q * 4 + 0) * SROW + row] = vx.x;
            sx[(q * 4 + 1) * SROW + row] = vx.y;
            sx[(q * 4 + 2) * SROW + row] = vx.z;
            sx[(q * 4 + 3) * SROW + row] = vx.w;
            se[(q * 4 + 0) * SROW + row] = ve.x;
            se[(q * 4 + 1) * SROW + row] = ve.y;
            se[(q * 4 + 2) * SROW + row] = ve.z;
            se[(q * 4 + 3) * SROW + row] = ve.w;
        }
        __syncthreads();

        #pragma unroll 4
        for (int d = 0; d < DCHUNK; ++d) {
            const float4 xa = *reinterpret_cast<const float4*>(&sx[d * SROW + ty * 4]);
            const float4 xb = *reinterpret_cast<const float4*>(&sx[d * SROW + 64 + ty * 4]);
            const float4 ea = *reinterpret_cast<const float4*>(&se[d * SROW + tx * 4]);
            const float4 eb = *reinterpret_cast<const float4*>(&se[d * SROW + 64 + tx * 4]);
            const float xv[8] = {xa.x, xa.y, xa.z, xa.w, xb.x, xb.y, xb.z, xb.w};
            const float ev[8] = {ea.x, ea.y, ea.z, ea.w, eb.x, eb.y, eb.z, eb.w};
            #pragma unroll
            for (int i = 0; i < 8; ++i)
                #pragma unroll
                for (int j = 0; j < 8; ++j)
                    acc[i][j] += fminf(xv[i], ev[j]);   // FMNMX (alu) + FADD (fma)
        }
    }

    // Epilogue: dist = SumX + SumE - 2*acc ; out = exp(-C*dist)
    float sxr[8], ser[8];
    #pragma unroll
    for (int i = 0; i < 8; ++i) {
        const int ri = (i < 4) ? (ty * 4 + i) : (64 + ty * 4 + (i - 4));
        sxr[i] = g_sumx[b0 + ri];
    }
    #pragma unroll
    for (int j = 0; j < 8; ++j) {
        const int cj = (j < 4) ? (tx * 4 + j) : (64 + tx * 4 + (j - 4));
        ser[j] = g_sume[e0 + cj];
    }

    #pragma unroll
    for (int i = 0; i < 8; ++i) {
        const int ri = (i < 4) ? (ty * 4 + i) : (64 + ty * 4 + (i - 4));
        float4 v0, v1;
        float res[8];
        #pragma unroll
        for (int j = 0; j < 8; ++j) {
            const float dist = sxr[i] + ser[j] - 2.f * acc[i][j];
            res[j] = __expf(-SPEC_C * dist);
        }
        v0 = make_float4(res[0], res[1], res[2], res[3]);
        v1 = make_float4(res[4], res[5], res[6], res[7]);
        float* orow = out + (size_t)(b0 + ri) * NE + e0;
        *reinterpret_cast<float4*>(&orow[tx * 4])      = v0;
        *reinterpret_cast<float4*>(&orow[64 + tx * 4]) = v1;
    }
}

// ---------------------------------------------------------------------------
extern "C" void kernel_launch(void* const* d_in, const int* in_sizes, int n_in,
                              void* d_out, int out_size) {
    const float* X    = (const float*)d_in[0];  // (2048,128)
    const float* E    = (const float*)d_in[1];  // (2048,128)
    const float* attn = (const float*)d_in[2];  // (128,)
    float* out = (float*)d_out;                 // (2048,2048)

    dim3 gprep(BATCH / 8, 2);
    prep_kernel<<<gprep, 256>>>(X, E, attn);

    dim3 gmain(NE / TILE, BATCH / TILE);
    alcove_kernel<<<gmain, 256>>>(out);
}